// round 10
// baseline (speedup 1.0000x reference)
#include <cuda_runtime.h>
#include <cfloat>
#include <cstdint>

#define R_    512
#define K_    17
#define HIN   56
#define OUT   96
#define NT    192
#define MPC   4                    // maps per CTA
#define NMAP  (R_ * K_)
#define TS    68                   // tmp row stride in words
#define PAD   4                    // col c stored at word c+4

// ---- compile-time bicubic helpers (period 12 for 56->96) ----
__host__ __device__ constexpr float cubicw_c(float x) {
    x = x < 0.f ? -x : x;
    float nearw = (1.25f * x - 2.25f) * x * x + 1.0f;
    float farw  = -0.75f * (((x - 5.0f) * x + 8.0f) * x - 4.0f);
    return x <= 1.0f ? nearw : farw;
}
__host__ __device__ constexpr float srcf(int t) {
    return ((float)t + 0.5f) * (56.0f / 96.0f) - 0.5f;
}
__host__ __device__ constexpr int ifloorf_c(float x) {
    int i = (int)x;
    return ((float)i > x) ? i - 1 : i;
}
__host__ __device__ constexpr int bofs(int t) { return ifloorf_c(srcf(t)); }
__host__ __device__ constexpr int brel(int T) { return 7 * (T / 12) + bofs(T % 12); }
__host__ __device__ constexpr float wgt(int t, int k) {
    return cubicw_c(srcf(t) - (float)(bofs(t) - 1 + k));
}

struct WTab { float w[12][4]; int b[12]; };
__host__ __device__ constexpr WTab make_wtab() {
    WTab r{};
    for (int t = 0; t < 12; ++t) {
        r.b[t] = bofs(t);
        for (int k = 0; k < 4; ++k) r.w[t][k] = wgt(t, k);
    }
    return r;
}
__constant__ WTab cWT = make_wtab();

// ---- cp.async 16B helper ----
__device__ __forceinline__ void cp16(unsigned int sdst, const void* gsrc) {
    asm volatile("cp.async.cg.shared.global [%0], [%1], 16;" :: "r"(sdst), "l"(gsrc));
}
__device__ __forceinline__ void cp_commit() {
    asm volatile("cp.async.commit_group;");
}
__device__ __forceinline__ void cp_wait0() {
    asm volatile("cp.async.wait_group 0;");
}

// clamped row load from the smem-staged mask
__device__ __forceinline__ float4 ldrow4s(const float* __restrict__ sm, int row) {
    row = min(max(row, 0), HIN - 1);
    return *(const float4*)(sm + row * HIN);
}

// -------- pass 1: vertical 56->96, float4 lanes, depth-1 row prefetch --------
template<int T>
__device__ __forceinline__ void p1_all(
    float4& m0, float4& m1, float4& m2, float4& m3, float4& nxt,
    const float* __restrict__ sm, int g7, float* __restrict__ dst,
    bool isL, bool isR)
{
    if constexpr (T < 12) {
        if constexpr (T == 0) {
            m0 = ldrow4s(sm, g7 + bofs(0) - 1);
            m1 = ldrow4s(sm, g7 + bofs(0)    );
            m2 = ldrow4s(sm, g7 + bofs(0) + 1);
            m3 = ldrow4s(sm, g7 + bofs(0) + 2);
        } else if constexpr (bofs(T) != bofs(T - 1)) {   // consume prefetched row
            m0 = m1; m1 = m2; m2 = m3; m3 = nxt;
        }
        // prefetch the row needed at step T+1 (consumed one iteration later)
        if constexpr (T + 1 < 12 && bofs(T + 1) != bofs(T))
            nxt = ldrow4s(sm, g7 + bofs(T + 1) + 2);

        constexpr float W0 = wgt(T, 0), W1 = wgt(T, 1), W2 = wgt(T, 2), W3 = wgt(T, 3);
        float4 v;
        v.x = fmaf(m3.x, W3, fmaf(m2.x, W2, fmaf(m1.x, W1, m0.x * W0)));
        v.y = fmaf(m3.y, W3, fmaf(m2.y, W2, fmaf(m1.y, W1, m0.y * W0)));
        v.z = fmaf(m3.z, W3, fmaf(m2.z, W2, fmaf(m1.z, W1, m0.z * W0)));
        v.w = fmaf(m3.w, W3, fmaf(m2.w, W2, fmaf(m1.w, W1, m0.w * W0)));
        *(float4*)(dst + T * TS) = v;
        if (isL) *(float2*)(dst + T * TS - 2) = make_float2(v.x, v.x); // cols -2,-1
        if (isR) *(float2*)(dst + T * TS + 4) = make_float2(v.w, v.w); // cols 56,57
        p1_all<T + 1>(m0, m1, m2, m3, nxt, sm, g7, dst, isL, isR);
    }
}

// ---------------- pass 2: hoisted loads, then pure FFMA sweep ----------------
template<int T>
__device__ __forceinline__ float p2v(const float* __restrict__ row) {
    constexpr int   t = T % 12;
    constexpr int   b = brel(T) + 3;
    constexpr float W0 = wgt(t, 0), W1 = wgt(t, 1), W2 = wgt(t, 2), W3 = wgt(t, 3);
    return fmaf(row[b + 3], W3, fmaf(row[b + 2], W2, fmaf(row[b + 1], W1, row[b] * W0)));
}
template<int G>
__device__ __forceinline__ void p2group(
    const float* __restrict__ row, float& best, int& bestGS, int baseIdx)
{
    if constexpr (G < 12) {
        float v0 = p2v<4 * G + 0>(row);
        float v1 = p2v<4 * G + 1>(row);
        float v2 = p2v<4 * G + 2>(row);
        float v3 = p2v<4 * G + 3>(row);
        float gm = fmaxf(fmaxf(v0, v1), fmaxf(v2, v3));
        if (gm > best) { best = gm; bestGS = baseIdx + 4 * G; } // strict '>': earliest group
        p2group<G + 1>(row, best, bestGS, baseIdx);
    }
}

__global__ __launch_bounds__(NT) void kp_kernel(
    const float* __restrict__ masks,
    const float* __restrict__ boxes,
    float* __restrict__ out)
{
    __shared__ float s_mask[HIN * HIN];    // 12.25 KB (cp.async staged)
    __shared__ float s_tmp[OUT * TS];      // 26.1 KB
    __shared__ float s_rv[NT / 32];
    __shared__ int   s_ri[NT / 32];

    const int tid  = threadIdx.x;
    const int map0 = blockIdx.x * MPC;

    unsigned int smask_u = (unsigned int)__cvta_generic_to_shared(s_mask);

    // prologue: prefetch map0's mask (784 float4 = 12.25 KB)
    {
        const float4* g = (const float4*)(masks + (size_t)map0 * (HIN * HIN));
        #pragma unroll
        for (int i = 0; i < 4; i++)
            cp16(smask_u + (tid + i * NT) * 16, g + tid + i * NT);
        if (tid < 16)
            cp16(smask_u + (768 + tid) * 16, g + 768 + tid);
        cp_commit();
    }

    for (int m = 0; m < MPC; m++) {
        const int map = map0 + m;

        cp_wait0();
        __syncthreads();    // mask visible to all; protects s_tmp/s_rv reuse

        // ---- pass 1: 112 threads, (row-block g, column quad q), smem->smem ----
        if (tid < 112) {
            int g = tid / 14;          // 0..7 : 12 output rows each
            int q = tid - g * 14;      // 0..13: cols 4q..4q+3
            const float* sm = s_mask + 4 * q;
            float* dst = s_tmp + (12 * g) * TS + PAD + 4 * q;
            float4 m0, m1, m2, m3, nxt;
            p1_all<0>(m0, m1, m2, m3, nxt, sm, 7 * g, dst, q == 0, q == 13);
        }
        __syncthreads();

        // ---- prefetch next map's mask (overlaps pass 2) ----
        if (m + 1 < MPC) {
            const float4* g = (const float4*)(masks + (size_t)(map + 1) * (HIN * HIN));
            #pragma unroll
            for (int i = 0; i < 4; i++)
                cp16(smask_u + (tid + i * NT) * 16, g + tid + i * NT);
            if (tid < 16)
                cp16(smask_u + (768 + tid) * 16, g + 768 + tid);
        }
        cp_commit();

        // ---- pass 2: hoist all 9 LDS.128, then grouped argmax sweep ----
        float best = -FLT_MAX;
        int bestGS = 0x7fffffff;
        {
            int h    = tid >> 1;
            int half = tid & 1;
            const float4* src = (const float4*)(s_tmp + h * TS + 28 * half);
            float row[36];
            #pragma unroll
            for (int c = 0; c < 9; c++) {         // back-to-back LDS.128 (MLP)
                float4 qv = src[c];
                row[4 * c + 0] = qv.x; row[4 * c + 1] = qv.y;
                row[4 * c + 2] = qv.z; row[4 * c + 3] = qv.w;
            }
            p2group<0>(row, best, bestGS, h * OUT + 48 * half);
        }

        #pragma unroll
        for (int off = 16; off > 0; off >>= 1) {
            float ov = __shfl_down_sync(0xffffffffu, best, off);
            int   og = __shfl_down_sync(0xffffffffu, bestGS, off);
            if (ov > best || (ov == best && og < bestGS)) { best = ov; bestGS = og; }
        }
        if ((tid & 31) == 0) { s_rv[tid >> 5] = best; s_ri[tid >> 5] = bestGS; }
        __syncthreads();

        if (tid == 0) {
            #pragma unroll
            for (int i = 1; i < NT / 32; i++) {
                float ov = s_rv[i]; int og = s_ri[i];
                if (ov > best || (ov == best && og < bestGS)) { best = ov; bestGS = og; }
            }
            // exact within-group index recovery (bit-identical recompute)
            int gs = bestGS;
            int hh = gs / OUT;
            int w0 = gs - hh * OUT;
            int found = 0;
            #pragma unroll
            for (int i = 3; i >= 0; i--) {    // descending: final 'found' = first match
                int T = w0 + i;
                int d = T / 12;
                int t = T - 12 * d;
                const float* p = s_tmp + hh * TS + 7 * d + cWT.b[t] + 3;
                float v = fmaf(p[3], cWT.w[t][3],
                          fmaf(p[2], cWT.w[t][2],
                          fmaf(p[1], cWT.w[t][1], p[0] * cWT.w[t][0])));
                if (v == best) { found = i; }
            }
            int bestIdx = gs + found;

            int r = map / K_;
            int k = map - r * K_;
            float b0 = boxes[r * 4 + 0];
            float b1 = boxes[r * 4 + 1];
            float b2 = boxes[r * 4 + 2];
            float b3 = boxes[r * 4 + 3];
            float len0 = fmaxf(b2 - b0, 1.0f);
            float len1 = fmaxf(b3 - b1, 1.0f);
            int y = bestIdx / OUT;
            int x = bestIdx - y * OUT;
            float p0 = ((float)y + 0.5f) * (len0 / (float)OUT) + b0;
            float p1 = ((float)x + 0.5f) * (len1 / (float)OUT) + b1;

            float* pred   = out;                    // [R, 3, K]
            float* scores = out + R_ * 3 * K_;      // [R, K]
            pred[r * 3 * K_ + 0 * K_ + k] = p0;
            pred[r * 3 * K_ + 1 * K_ + k] = p1;
            pred[r * 3 * K_ + 2 * K_ + k] = 1.0f;
            scores[r * K_ + k] = best;
        }
    }
}

extern "C" void kernel_launch(void* const* d_in, const int* in_sizes, int n_in,
                              void* d_out, int out_size) {
    const float* masks = (const float*)d_in[0];   // [512,17,56,56] f32
    const float* boxes = (const float*)d_in[1];   // [512,4] f32
    float* out = (float*)d_out;
    kp_kernel<<<NMAP / MPC, NT>>>(masks, boxes, out);
}

// round 11
// speedup vs baseline: 1.0838x; 1.0838x over previous
#include <cuda_runtime.h>
#include <cfloat>
#include <cstdint>

#define R_    512
#define K_    17
#define HIN   56
#define OUT   96
#define NT    192
#define MPC   4                    // maps per CTA
#define NMAP  (R_ * K_)
#define TS    68                   // tmp row stride in words
#define PAD   4                    // col c stored at word c+4

// ---- compile-time bicubic helpers (period 12 for 56->96) ----
__host__ __device__ constexpr float cubicw_c(float x) {
    x = x < 0.f ? -x : x;
    float nearw = (1.25f * x - 2.25f) * x * x + 1.0f;
    float farw  = -0.75f * (((x - 5.0f) * x + 8.0f) * x - 4.0f);
    return x <= 1.0f ? nearw : farw;
}
__host__ __device__ constexpr float srcf(int t) {
    return ((float)t + 0.5f) * (56.0f / 96.0f) - 0.5f;
}
__host__ __device__ constexpr int ifloorf_c(float x) {
    int i = (int)x;
    return ((float)i > x) ? i - 1 : i;
}
__host__ __device__ constexpr int bofs(int t) { return ifloorf_c(srcf(t)); }
__host__ __device__ constexpr int brel(int T) { return 7 * (T / 12) + bofs(T % 12); }
__host__ __device__ constexpr float wgt(int t, int k) {
    return cubicw_c(srcf(t) - (float)(bofs(t) - 1 + k));
}
__host__ __device__ constexpr int slot(int R) { return ((R % 4) + 4) % 4; }

struct WTab { float w[12][4]; int b[12]; };
__host__ __device__ constexpr WTab make_wtab() {
    WTab r{};
    for (int t = 0; t < 12; ++t) {
        r.b[t] = bofs(t);
        for (int k = 0; k < 4; ++k) r.w[t][k] = wgt(t, k);
    }
    return r;
}
__constant__ WTab cWT = make_wtab();

// ---- cp.async 16B helper ----
__device__ __forceinline__ void cp16(unsigned int sdst, const void* gsrc) {
    asm volatile("cp.async.cg.shared.global [%0], [%1], 16;" :: "r"(sdst), "l"(gsrc));
}
__device__ __forceinline__ void cp_commit() {
    asm volatile("cp.async.commit_group;");
}
__device__ __forceinline__ void cp_wait0() {
    asm volatile("cp.async.wait_group 0;");
}

// clamped row load from the smem-staged mask
__device__ __forceinline__ float4 ldrow4s(const float* __restrict__ sm, int row) {
    row = min(max(row, 0), HIN - 1);
    return *(const float4*)(sm + row * HIN);
}

// -------- pass 1: vertical 56->96, float4 lanes, cyclic register window -----
// row R (relative) permanently lives in slot R mod 4 -> zero slide MOVs.
template<int T>
__device__ __forceinline__ void p1_all(
    float4 (&r)[4], const float* __restrict__ sm, int g7, float* __restrict__ dst)
{
    if constexpr (T < 12) {
        constexpr int b = bofs(T);
        if constexpr (T == 0) {
            r[slot(b - 1)] = ldrow4s(sm, g7 + b - 1);
            r[slot(b    )] = ldrow4s(sm, g7 + b    );
            r[slot(b + 1)] = ldrow4s(sm, g7 + b + 1);
            r[slot(b + 2)] = ldrow4s(sm, g7 + b + 2);
        } else if constexpr (bofs(T) != bofs(T - 1)) {   // base advances by <=1
            r[slot(b + 2)] = ldrow4s(sm, g7 + b + 2);
        }
        constexpr int s0 = slot(b - 1), s1 = slot(b), s2 = slot(b + 1), s3 = slot(b + 2);
        constexpr float W0 = wgt(T, 0), W1 = wgt(T, 1), W2 = wgt(T, 2), W3 = wgt(T, 3);
        float4 v;
        v.x = fmaf(r[s3].x, W3, fmaf(r[s2].x, W2, fmaf(r[s1].x, W1, r[s0].x * W0)));
        v.y = fmaf(r[s3].y, W3, fmaf(r[s2].y, W2, fmaf(r[s1].y, W1, r[s0].y * W0)));
        v.z = fmaf(r[s3].z, W3, fmaf(r[s2].z, W2, fmaf(r[s1].z, W1, r[s0].z * W0)));
        v.w = fmaf(r[s3].w, W3, fmaf(r[s2].w, W2, fmaf(r[s1].w, W1, r[s0].w * W0)));
        *(float4*)(dst + T * TS) = v;        // no border stores (patched in pass 2)
        p1_all<T + 1>(r, sm, g7, dst);
    }
}

// ---------------- pass 2: JIT chunk loads + in-register border patch --------
template<int C, int HI>
__device__ __forceinline__ void p2chunks(float* __restrict__ row, const float4* __restrict__ src) {
    if constexpr (C <= HI) {
        float4 q = src[C];
        row[4 * C + 0] = q.x; row[4 * C + 1] = q.y;
        row[4 * C + 2] = q.z; row[4 * C + 3] = q.w;
        p2chunks<C + 1, HI>(row, src);
    }
}
template<int T>
__device__ __forceinline__ void p2load(float* __restrict__ row, const float4* __restrict__ src,
                                       int half) {
    constexpr int hi = (brel(T) + 6) / 4;
    constexpr int lo = (T == 0) ? 0 : (brel(T - 1) + 6) / 4 + 1;
    p2chunks<lo, hi>(row, src);
    if constexpr (T == 0) {
        // left border (cols -2,-1 = words 2,3) := col 0 (word 4); chunks 0,1 resident
        if (half == 0) { row[2] = row[4]; row[3] = row[4]; }
    }
    if constexpr (T > 0 && (brel(T - 1) + 6) / 4 < 8 && (brel(T) + 6) / 4 >= 8) {
        // right border (cols 56,57 = words 60,61) := col 55 (word 59); chunk 8 just loaded
        if (half != 0) { row[32] = row[31]; row[33] = row[31]; }
    }
}
template<int T>
__device__ __forceinline__ float p2v(const float* __restrict__ row) {
    constexpr int   t = T % 12;
    constexpr int   b = brel(T) + 3;
    constexpr float W0 = wgt(t, 0), W1 = wgt(t, 1), W2 = wgt(t, 2), W3 = wgt(t, 3);
    return fmaf(row[b + 3], W3, fmaf(row[b + 2], W2, fmaf(row[b + 1], W1, row[b] * W0)));
}
template<int G>
__device__ __forceinline__ void p2group(
    float* __restrict__ row, const float4* __restrict__ src, int half,
    float& best, int& bestGS, int baseIdx)
{
    if constexpr (G < 12) {
        p2load<4 * G + 0>(row, src, half); float v0 = p2v<4 * G + 0>(row);
        p2load<4 * G + 1>(row, src, half); float v1 = p2v<4 * G + 1>(row);
        p2load<4 * G + 2>(row, src, half); float v2 = p2v<4 * G + 2>(row);
        p2load<4 * G + 3>(row, src, half); float v3 = p2v<4 * G + 3>(row);
        float gm = fmaxf(fmaxf(v0, v1), fmaxf(v2, v3));
        if (gm > best) { best = gm; bestGS = baseIdx + 4 * G; } // strict '>': earliest group
        p2group<G + 1>(row, src, half, best, bestGS, baseIdx);
    }
}

__global__ __launch_bounds__(NT) void kp_kernel(
    const float* __restrict__ masks,
    const float* __restrict__ boxes,
    float* __restrict__ out)
{
    __shared__ float s_mask[HIN * HIN];    // 12.25 KB (cp.async staged)
    __shared__ float s_tmp[OUT * TS];      // 26.1 KB
    __shared__ float s_rv[NT / 32];
    __shared__ int   s_ri[NT / 32];

    const int tid  = threadIdx.x;
    const int map0 = blockIdx.x * MPC;

    unsigned int smask_u = (unsigned int)__cvta_generic_to_shared(s_mask);

    // prologue: prefetch map0's mask (784 float4 = 12.25 KB)
    {
        const float4* g = (const float4*)(masks + (size_t)map0 * (HIN * HIN));
        #pragma unroll
        for (int i = 0; i < 4; i++)
            cp16(smask_u + (tid + i * NT) * 16, g + tid + i * NT);
        if (tid < 16)
            cp16(smask_u + (768 + tid) * 16, g + 768 + tid);
        cp_commit();
    }

    for (int m = 0; m < MPC; m++) {
        const int map = map0 + m;
        const int r_  = map / K_;
        const int k_  = map - r_ * K_;
        // hoisted box load: latency hidden behind pass1+pass2
        const float4 bx = *(const float4*)(boxes + r_ * 4);

        cp_wait0();
        __syncthreads();    // mask visible to all; protects s_tmp/s_rv reuse

        // ---- pass 1: 112 threads, (row-block g, column quad q), smem->smem ----
        if (tid < 112) {
            int g = tid / 14;          // 0..7 : 12 output rows each
            int q = tid - g * 14;      // 0..13: cols 4q..4q+3
            const float* sm = s_mask + 4 * q;
            float* dst = s_tmp + (12 * g) * TS + PAD + 4 * q;
            float4 rwin[4];
            p1_all<0>(rwin, sm, 7 * g, dst);
        }
        __syncthreads();

        // ---- prefetch next map's mask (overlaps pass 2) ----
        if (m + 1 < MPC) {
            const float4* g = (const float4*)(masks + (size_t)(map + 1) * (HIN * HIN));
            #pragma unroll
            for (int i = 0; i < 4; i++)
                cp16(smask_u + (tid + i * NT) * 16, g + tid + i * NT);
            if (tid < 16)
                cp16(smask_u + (768 + tid) * 16, g + 768 + tid);
        }
        cp_commit();

        // ---- pass 2: horizontal 56->96 with grouped argmax ----
        float best = -FLT_MAX;
        int bestGS = 0x7fffffff;
        {
            int h    = tid >> 1;
            int half = tid & 1;
            const float4* src = (const float4*)(s_tmp + h * TS + 28 * half);
            float row[36];
            p2group<0>(row, src, half, best, bestGS, h * OUT + 48 * half);
        }

        #pragma unroll
        for (int off = 16; off > 0; off >>= 1) {
            float ov = __shfl_down_sync(0xffffffffu, best, off);
            int   og = __shfl_down_sync(0xffffffffu, bestGS, off);
            if (ov > best || (ov == best && og < bestGS)) { best = ov; bestGS = og; }
        }
        if ((tid & 31) == 0) { s_rv[tid >> 5] = best; s_ri[tid >> 5] = bestGS; }
        __syncthreads();

        if (tid == 0) {
            #pragma unroll
            for (int i = 1; i < NT / 32; i++) {
                float ov = s_rv[i]; int og = s_ri[i];
                if (ov > best || (ov == best && og < bestGS)) { best = ov; bestGS = og; }
            }
            // exact within-group index recovery (bit-identical recompute).
            // words clamped to [4,59]: identical bits to the register border patch.
            int gs = bestGS;
            int hh = gs / OUT;
            int w0 = gs - hh * OUT;
            const float* rowp = s_tmp + hh * TS;
            int found = 0;
            #pragma unroll
            for (int i = 3; i >= 0; i--) {    // descending: final 'found' = first match
                int T = w0 + i;
                int d = T / 12;
                int t = T - 12 * d;
                int base = 7 * d + cWT.b[t] + 3;
                float x0 = rowp[min(max(base + 0, 4), 59)];
                float x1 = rowp[min(max(base + 1, 4), 59)];
                float x2 = rowp[min(max(base + 2, 4), 59)];
                float x3 = rowp[min(max(base + 3, 4), 59)];
                float v = fmaf(x3, cWT.w[t][3],
                          fmaf(x2, cWT.w[t][2],
                          fmaf(x1, cWT.w[t][1], x0 * cWT.w[t][0])));
                if (v == best) { found = i; }
            }
            int bestIdx = gs + found;

            float len0 = fmaxf(bx.z - bx.x, 1.0f);
            float len1 = fmaxf(bx.w - bx.y, 1.0f);
            int y = bestIdx / OUT;
            int x = bestIdx - y * OUT;
            float p0 = ((float)y + 0.5f) * (len0 / (float)OUT) + bx.x;
            float p1 = ((float)x + 0.5f) * (len1 / (float)OUT) + bx.y;

            float* pred   = out;                    // [R, 3, K]
            float* scores = out + R_ * 3 * K_;      // [R, K]
            pred[r_ * 3 * K_ + 0 * K_ + k_] = p0;
            pred[r_ * 3 * K_ + 1 * K_ + k_] = p1;
            pred[r_ * 3 * K_ + 2 * K_ + k_] = 1.0f;
            scores[r_ * K_ + k_] = best;
        }
    }
}

extern "C" void kernel_launch(void* const* d_in, const int* in_sizes, int n_in,
                              void* d_out, int out_size) {
    const float* masks = (const float*)d_in[0];   // [512,17,56,56] f32
    const float* boxes = (const float*)d_in[1];   // [512,4] f32
    float* out = (float*)d_out;
    kp_kernel<<<NMAP / MPC, NT>>>(masks, boxes, out);
}

// round 12
// speedup vs baseline: 1.0899x; 1.0056x over previous
#include <cuda_runtime.h>
#include <cfloat>
#include <cstdint>

#define R_    512
#define K_    17
#define HIN   56
#define OUT   96
#define NT    224
#define MPC   4                    // maps per CTA
#define NMAP  (R_ * K_)
#define TS    56                   // tmp row stride = cols 0..55 exactly (16B aligned)

// ---- compile-time bicubic helpers (period 12 for 56->96) ----
__host__ __device__ constexpr float cubicw_c(float x) {
    x = x < 0.f ? -x : x;
    float nearw = (1.25f * x - 2.25f) * x * x + 1.0f;
    float farw  = -0.75f * (((x - 5.0f) * x + 8.0f) * x - 4.0f);
    return x <= 1.0f ? nearw : farw;
}
__host__ __device__ constexpr float srcf(int t) {
    return ((float)t + 0.5f) * (56.0f / 96.0f) - 0.5f;
}
__host__ __device__ constexpr int ifloorf_c(float x) {
    int i = (int)x;
    return ((float)i > x) ? i - 1 : i;
}
__host__ __device__ constexpr int bofs(int t) { return ifloorf_c(srcf(t)); }
__host__ __device__ constexpr int brel(int T) { return 7 * (T / 12) + bofs(T % 12); }
__host__ __device__ constexpr float wgt(int t, int k) {
    return cubicw_c(srcf(t) - (float)(bofs(t) - 1 + k));
}
__host__ __device__ constexpr int slot(int R) { return ((R % 4) + 4) % 4; }
__host__ __device__ constexpr int clampi(int v, int lo, int hi) {
    return v < lo ? lo : (v > hi ? hi : v);
}

struct WTab { float w[12][4]; int b[12]; };
__host__ __device__ constexpr WTab make_wtab() {
    WTab r{};
    for (int t = 0; t < 12; ++t) {
        r.b[t] = bofs(t);
        for (int k = 0; k < 4; ++k) r.w[t][k] = wgt(t, k);
    }
    return r;
}
__constant__ WTab cWT = make_wtab();

// ---- cp.async 16B helper ----
__device__ __forceinline__ void cp16(unsigned int sdst, const void* gsrc) {
    asm volatile("cp.async.cg.shared.global [%0], [%1], 16;" :: "r"(sdst), "l"(gsrc));
}
__device__ __forceinline__ void cp_commit() {
    asm volatile("cp.async.commit_group;");
}
__device__ __forceinline__ void cp_wait0() {
    asm volatile("cp.async.wait_group 0;");
}

__device__ __forceinline__ void prefetch_mask(unsigned int smask_u,
                                              const float* __restrict__ masks,
                                              int map, int tid) {
    const float4* g = (const float4*)(masks + (size_t)map * (HIN * HIN));
    #pragma unroll
    for (int i = 0; i < 3; i++)
        cp16(smask_u + (tid + i * NT) * 16, g + tid + i * NT);
    if (tid < 112)
        cp16(smask_u + (672 + tid) * 16, g + 672 + tid);
}

// clamped row load from the smem-staged mask
__device__ __forceinline__ float4 ldrow4s(const float* __restrict__ sm, int row) {
    row = min(max(row, 0), HIN - 1);
    return *(const float4*)(sm + row * HIN);
}

// -------- pass 1: vertical 56->96, float4 lanes, cyclic register window -----
// team covers outputs T in [T0, TEND) of a 12-row period block.
template<int T, int T0, int TEND>
__device__ __forceinline__ void p1_team(
    float4 (&r)[4], const float* __restrict__ sm, int g7, float* __restrict__ dst)
{
    if constexpr (T < TEND) {
        constexpr int b = bofs(T);
        if constexpr (T == T0) {
            r[slot(b - 1)] = ldrow4s(sm, g7 + b - 1);
            r[slot(b    )] = ldrow4s(sm, g7 + b    );
            r[slot(b + 1)] = ldrow4s(sm, g7 + b + 1);
            r[slot(b + 2)] = ldrow4s(sm, g7 + b + 2);
        } else if constexpr (bofs(T) != bofs(T - 1)) {   // base advances by <=1
            r[slot(b + 2)] = ldrow4s(sm, g7 + b + 2);
        }
        constexpr int s0 = slot(b - 1), s1 = slot(b), s2 = slot(b + 1), s3 = slot(b + 2);
        constexpr float W0 = wgt(T, 0), W1 = wgt(T, 1), W2 = wgt(T, 2), W3 = wgt(T, 3);
        float4 v;
        v.x = fmaf(r[s3].x, W3, fmaf(r[s2].x, W2, fmaf(r[s1].x, W1, r[s0].x * W0)));
        v.y = fmaf(r[s3].y, W3, fmaf(r[s2].y, W2, fmaf(r[s1].y, W1, r[s0].y * W0)));
        v.z = fmaf(r[s3].z, W3, fmaf(r[s2].z, W2, fmaf(r[s1].z, W1, r[s0].z * W0)));
        v.w = fmaf(r[s3].w, W3, fmaf(r[s2].w, W2, fmaf(r[s1].w, W1, r[s0].w * W0)));
        *(float4*)(dst + T * TS) = v;
        p1_team<T + 1, T0, TEND>(r, sm, g7, dst);
    }
}

// ---------------- pass 2: JIT chunk loads, compile-time clamped taps --------
// HALF 0: row[j] = word j   (cols 0..31);  taps at clamp(brel(T)-1+k, >=0)
// HALF 1: row[j] = word 24+j (cols 24..55); taps at clamp(brel(T)+3+k, <=31)
template<int T, int HALF>
__host__ __device__ constexpr int hiword() {          // highest local word for T
    return HALF == 0 ? (brel(T) + 2) : clampi(brel(T) + 6, 0, 31);
}
template<int C, int HI>
__device__ __forceinline__ void p2chunks(float* __restrict__ row, const float4* __restrict__ src) {
    if constexpr (C <= HI) {
        float4 q = src[C];
        row[4 * C + 0] = q.x; row[4 * C + 1] = q.y;
        row[4 * C + 2] = q.z; row[4 * C + 3] = q.w;
        p2chunks<C + 1, HI>(row, src);
    }
}
template<int T, int HALF>
__device__ __forceinline__ void p2load(float* __restrict__ row, const float4* __restrict__ src) {
    constexpr int hi = hiword<T, HALF>() / 4;
    constexpr int lo = (T == 0) ? 0 : hiword<T - 1, HALF>() / 4 + 1;
    p2chunks<lo, hi>(row, src);
}
template<int T, int HALF>
__device__ __forceinline__ float p2v(const float* __restrict__ row) {
    constexpr int t = T % 12;
    constexpr int i0 = (HALF == 0) ? clampi(brel(T) - 1, 0, 31) : clampi(brel(T) + 3, 0, 31);
    constexpr int i1 = (HALF == 0) ? clampi(brel(T)    , 0, 31) : clampi(brel(T) + 4, 0, 31);
    constexpr int i2 = (HALF == 0) ? clampi(brel(T) + 1, 0, 31) : clampi(brel(T) + 5, 0, 31);
    constexpr int i3 = (HALF == 0) ? clampi(brel(T) + 2, 0, 31) : clampi(brel(T) + 6, 0, 31);
    constexpr float W0 = wgt(t, 0), W1 = wgt(t, 1), W2 = wgt(t, 2), W3 = wgt(t, 3);
    return fmaf(row[i3], W3, fmaf(row[i2], W2, fmaf(row[i1], W1, row[i0] * W0)));
}
template<int G, int HALF>
__device__ __forceinline__ void p2group(
    float* __restrict__ row, const float4* __restrict__ src,
    float& best, int& bestGS, int baseIdx)
{
    if constexpr (G < 12) {
        p2load<4 * G + 0, HALF>(row, src); float v0 = p2v<4 * G + 0, HALF>(row);
        p2load<4 * G + 1, HALF>(row, src); float v1 = p2v<4 * G + 1, HALF>(row);
        p2load<4 * G + 2, HALF>(row, src); float v2 = p2v<4 * G + 2, HALF>(row);
        p2load<4 * G + 3, HALF>(row, src); float v3 = p2v<4 * G + 3, HALF>(row);
        float gm = fmaxf(fmaxf(v0, v1), fmaxf(v2, v3));
        if (gm > best) { best = gm; bestGS = baseIdx + 4 * G; } // strict '>': earliest group
        p2group<G + 1, HALF>(row, src, best, bestGS, baseIdx);
    }
}

__global__ void __launch_bounds__(NT, 6) kp_kernel(
    const float* __restrict__ masks,
    const float* __restrict__ boxes,
    float* __restrict__ out)
{
    __shared__ float s_mask[HIN * HIN];    // 12.25 KB (cp.async staged)
    __shared__ float s_tmp[OUT * TS];      // 21 KB
    __shared__ float s_rv[NT / 32];
    __shared__ int   s_ri[NT / 32];

    const int tid  = threadIdx.x;
    const int map0 = blockIdx.x * MPC;

    unsigned int smask_u = (unsigned int)__cvta_generic_to_shared(s_mask);

    prefetch_mask(smask_u, masks, map0, tid);
    cp_commit();

    for (int m = 0; m < MPC; m++) {
        const int map = map0 + m;
        const int r_  = map / K_;
        const int k_  = map - r_ * K_;
        const float4 bx = *(const float4*)(boxes + r_ * 4);   // hoisted box load

        cp_wait0();
        __syncthreads();    // mask visible; s_tmp/s_rv free

        // ---- pass 1: 224 threads, two teams split each 12-row period ----
        {
            int team = tid / 112;            // 0: outputs T=0..5, 1: T=6..11
            int rr   = tid - team * 112;
            int g = rr / 14;                 // 0..7 period block
            int q = rr - g * 14;             // 0..13 column quad
            const float* sm = s_mask + 4 * q;
            float* dst = s_tmp + (12 * g) * TS + 4 * q;
            float4 rwin[4];
            if (team == 0) p1_team<0, 0, 6 >(rwin, sm, 7 * g, dst);
            else           p1_team<6, 6, 12>(rwin, sm, 7 * g, dst);
        }
        __syncthreads();

        // ---- prefetch next map's mask (overlaps pass 2) ----
        if (m + 1 < MPC) prefetch_mask(smask_u, masks, map + 1, tid);
        cp_commit();

        // ---- pass 2: horizontal 56->96 with grouped argmax ----
        // half by 96-thread group (warp-uniform); warp 6 idles here
        float best = -FLT_MAX;
        int bestGS = 0x7fffffff;
        if (tid < 192) {
            int half = tid / 96;
            int h    = tid - half * 96;
            float row[32];
            if (half == 0) {
                const float4* src = (const float4*)(s_tmp + h * TS);
                p2group<0, 0>(row, src, best, bestGS, h * OUT);
            } else {
                const float4* src = (const float4*)(s_tmp + h * TS + 24);
                p2group<0, 1>(row, src, best, bestGS, h * OUT + 48);
            }
        }

        #pragma unroll
        for (int off = 16; off > 0; off >>= 1) {
            float ov = __shfl_down_sync(0xffffffffu, best, off);
            int   og = __shfl_down_sync(0xffffffffu, bestGS, off);
            if (ov > best || (ov == best && og < bestGS)) { best = ov; bestGS = og; }
        }
        if ((tid & 31) == 0) { s_rv[tid >> 5] = best; s_ri[tid >> 5] = bestGS; }
        __syncthreads();

        if (tid == 0) {
            #pragma unroll
            for (int i = 1; i < NT / 32; i++) {
                float ov = s_rv[i]; int og = s_ri[i];
                if (ov > best || (ov == best && og < bestGS)) { best = ov; bestGS = og; }
            }
            // exact within-group index recovery (bit-identical clamped recompute)
            int gs = bestGS;
            int hh = gs / OUT;
            int w0 = gs - hh * OUT;
            const float* rowp = s_tmp + hh * TS;
            int found = 0;
            #pragma unroll
            for (int i = 3; i >= 0; i--) {    // descending: final 'found' = first match
                int T = w0 + i;
                int d = T / 12;
                int t = T - 12 * d;
                int base = 7 * d + cWT.b[t] - 1;     // leftmost tap col
                float x0 = rowp[min(max(base + 0, 0), 55)];
                float x1 = rowp[min(max(base + 1, 0), 55)];
                float x2 = rowp[min(max(base + 2, 0), 55)];
                float x3 = rowp[min(max(base + 3, 0), 55)];
                float v = fmaf(x3, cWT.w[t][3],
                          fmaf(x2, cWT.w[t][2],
                          fmaf(x1, cWT.w[t][1], x0 * cWT.w[t][0])));
                if (v == best) { found = i; }
            }
            int bestIdx = gs + found;

            float len0 = fmaxf(bx.z - bx.x, 1.0f);
            float len1 = fmaxf(bx.w - bx.y, 1.0f);
            int y = bestIdx / OUT;
            int x = bestIdx - y * OUT;
            float p0 = ((float)y + 0.5f) * (len0 / (float)OUT) + bx.x;
            float p1 = ((float)x + 0.5f) * (len1 / (float)OUT) + bx.y;

            float* pred   = out;                    // [R, 3, K]
            float* scores = out + R_ * 3 * K_;      // [R, K]
            pred[r_ * 3 * K_ + 0 * K_ + k_] = p0;
            pred[r_ * 3 * K_ + 1 * K_ + k_] = p1;
            pred[r_ * 3 * K_ + 2 * K_ + k_] = 1.0f;
            scores[r_ * K_ + k_] = best;
        }
    }
}

extern "C" void kernel_launch(void* const* d_in, const int* in_sizes, int n_in,
                              void* d_out, int out_size) {
    const float* masks = (const float*)d_in[0];   // [512,17,56,56] f32
    const float* boxes = (const float*)d_in[1];   // [512,4] f32
    float* out = (float*)d_out;
    kp_kernel<<<NMAP / MPC, NT>>>(masks, boxes, out);
}

// round 13
// speedup vs baseline: 1.0907x; 1.0007x over previous
#include <cuda_runtime.h>
#include <cfloat>
#include <cstdint>

#define R_    512
#define K_    17
#define HIN   56
#define OUT   96
#define NT    224
#define MPC   4                    // maps per CTA
#define NMAP  (R_ * K_)
#define TS    56                   // tmp row stride (words)
#define MPAD  2                    // s_mask replicated border rows each side

// ---- compile-time bicubic helpers (period 12 for 56->96) ----
__host__ __device__ constexpr float cubicw_c(float x) {
    x = x < 0.f ? -x : x;
    float nearw = (1.25f * x - 2.25f) * x * x + 1.0f;
    float farw  = -0.75f * (((x - 5.0f) * x + 8.0f) * x - 4.0f);
    return x <= 1.0f ? nearw : farw;
}
__host__ __device__ constexpr float srcf(int t) {
    return ((float)t + 0.5f) * (56.0f / 96.0f) - 0.5f;
}
__host__ __device__ constexpr int ifloorf_c(float x) {
    int i = (int)x;
    return ((float)i > x) ? i - 1 : i;
}
__host__ __device__ constexpr int bofs(int t) { return ifloorf_c(srcf(t)); }
__host__ __device__ constexpr int brel(int T) { return 7 * (T / 12) + bofs(T % 12); }
__host__ __device__ constexpr float wgt(int t, int k) {
    return cubicw_c(srcf(t) - (float)(bofs(t) - 1 + k));
}
__host__ __device__ constexpr int slot(int R) { return ((R % 4) + 4) % 4; }
__host__ __device__ constexpr int clampi(int v, int lo, int hi) {
    return v < lo ? lo : (v > hi ? hi : v);
}

struct WTab { float w[12][4]; int b[12]; };
__host__ __device__ constexpr WTab make_wtab() {
    WTab r{};
    for (int t = 0; t < 12; ++t) {
        r.b[t] = bofs(t);
        for (int k = 0; k < 4; ++k) r.w[t][k] = wgt(t, k);
    }
    return r;
}
__constant__ WTab cWT = make_wtab();

// ---- cp.async helpers ----
__device__ __forceinline__ void cp16(unsigned int sdst, const void* gsrc) {
    asm volatile("cp.async.cg.shared.global [%0], [%1], 16;" :: "r"(sdst), "l"(gsrc));
}
__device__ __forceinline__ void cp_commit() { asm volatile("cp.async.commit_group;"); }
__device__ __forceinline__ void cp_wait0() { asm volatile("cp.async.wait_group 0;"); }

// prefetch the 56x56 mask into padded smem (rows -2..57, stride 56 words).
// pad rows: -2,-1 := row 0 ; 56,57 := row 55 (border replicate, bit-identical).
__device__ __forceinline__ void prefetch_mask(unsigned int smask_u,
                                              const float* __restrict__ masks,
                                              int map, int tid) {
    const float4* g = (const float4*)(masks + (size_t)map * (HIN * HIN));
    const unsigned int body = smask_u + MPAD * HIN * 4;   // row 0 at padded row 2
    #pragma unroll
    for (int i = 0; i < 3; i++)
        cp16(body + (tid + i * NT) * 16, g + tid + i * NT);
    if (tid < 112)
        cp16(body + (672 + tid) * 16, g + 672 + tid);
    else if (tid < 168) {
        int j = tid - 112;            // 0..55
        if (j < 28) {                 // top pad: rows 0,1 of padded array
            int p = j / 14, q = j - p * 14;
            cp16(smask_u + (p * HIN + 4 * q) * 4, g + q);
        } else {                      // bottom pad: rows 58,59
            int jj = j - 28;
            int p = jj / 14, q = jj - p * 14;
            cp16(smask_u + ((58 + p) * HIN + 4 * q) * 4, g + 770 + q);
        }
    }
}

// -------- pass 1: vertical 56->96, float4 lanes, cyclic window, NO clamps ---
// smg points at (padded) input row 7g, col 4q. All offsets compile-time.
template<int T, int T0, int TEND>
__device__ __forceinline__ void p1_team(
    float4 (&r)[4], const float* __restrict__ smg, float* __restrict__ dst)
{
    if constexpr (T < TEND) {
        constexpr int b = bofs(T);
        if constexpr (T == T0) {
            r[slot(b - 1)] = *(const float4*)(smg + (b - 1) * HIN);
            r[slot(b    )] = *(const float4*)(smg + (b    ) * HIN);
            r[slot(b + 1)] = *(const float4*)(smg + (b + 1) * HIN);
            r[slot(b + 2)] = *(const float4*)(smg + (b + 2) * HIN);
        } else if constexpr (bofs(T) != bofs(T - 1)) {
            r[slot(b + 2)] = *(const float4*)(smg + (b + 2) * HIN);
        }
        constexpr int s0 = slot(b - 1), s1 = slot(b), s2 = slot(b + 1), s3 = slot(b + 2);
        constexpr float W0 = wgt(T, 0), W1 = wgt(T, 1), W2 = wgt(T, 2), W3 = wgt(T, 3);
        float4 v;
        v.x = fmaf(r[s3].x, W3, fmaf(r[s2].x, W2, fmaf(r[s1].x, W1, r[s0].x * W0)));
        v.y = fmaf(r[s3].y, W3, fmaf(r[s2].y, W2, fmaf(r[s1].y, W1, r[s0].y * W0)));
        v.z = fmaf(r[s3].z, W3, fmaf(r[s2].z, W2, fmaf(r[s1].z, W1, r[s0].z * W0)));
        v.w = fmaf(r[s3].w, W3, fmaf(r[s2].w, W2, fmaf(r[s1].w, W1, r[s0].w * W0)));
        *(float4*)(dst + T * TS) = v;
        p1_team<T + 1, T0, TEND>(r, smg, dst);
    }
}

// ---------------- pass 2: JIT chunk loads, compile-time clamped taps --------
template<int T, int HALF>
__host__ __device__ constexpr int hiword() {
    return HALF == 0 ? (brel(T) + 2) : clampi(brel(T) + 6, 0, 31);
}
template<int C, int HI>
__device__ __forceinline__ void p2chunks(float* __restrict__ row, const float4* __restrict__ src) {
    if constexpr (C <= HI) {
        float4 q = src[C];
        row[4 * C + 0] = q.x; row[4 * C + 1] = q.y;
        row[4 * C + 2] = q.z; row[4 * C + 3] = q.w;
        p2chunks<C + 1, HI>(row, src);
    }
}
template<int T, int HALF>
__device__ __forceinline__ void p2load(float* __restrict__ row, const float4* __restrict__ src) {
    constexpr int hi = hiword<T, HALF>() / 4;
    constexpr int lo = (T == 0) ? 0 : hiword<T - 1, HALF>() / 4 + 1;
    p2chunks<lo, hi>(row, src);
}
template<int T, int HALF>
__device__ __forceinline__ float p2v(const float* __restrict__ row) {
    constexpr int t = T % 12;
    constexpr int i0 = (HALF == 0) ? clampi(brel(T) - 1, 0, 31) : clampi(brel(T) + 3, 0, 31);
    constexpr int i1 = (HALF == 0) ? clampi(brel(T)    , 0, 31) : clampi(brel(T) + 4, 0, 31);
    constexpr int i2 = (HALF == 0) ? clampi(brel(T) + 1, 0, 31) : clampi(brel(T) + 5, 0, 31);
    constexpr int i3 = (HALF == 0) ? clampi(brel(T) + 2, 0, 31) : clampi(brel(T) + 6, 0, 31);
    constexpr float W0 = wgt(t, 0), W1 = wgt(t, 1), W2 = wgt(t, 2), W3 = wgt(t, 3);
    return fmaf(row[i3], W3, fmaf(row[i2], W2, fmaf(row[i1], W1, row[i0] * W0)));
}
// supergroups of 8 contiguous outputs (tie-break stays exact: ascending ranges)
template<int G, int HALF>
__device__ __forceinline__ void p2super(
    float* __restrict__ row, const float4* __restrict__ src,
    float& best, int& bestGS, int baseIdx)
{
    if constexpr (G < 6) {
        p2load<8 * G + 0, HALF>(row, src); float v0 = p2v<8 * G + 0, HALF>(row);
        p2load<8 * G + 1, HALF>(row, src); float v1 = p2v<8 * G + 1, HALF>(row);
        p2load<8 * G + 2, HALF>(row, src); float v2 = p2v<8 * G + 2, HALF>(row);
        p2load<8 * G + 3, HALF>(row, src); float v3 = p2v<8 * G + 3, HALF>(row);
        p2load<8 * G + 4, HALF>(row, src); float v4 = p2v<8 * G + 4, HALF>(row);
        p2load<8 * G + 5, HALF>(row, src); float v5 = p2v<8 * G + 5, HALF>(row);
        p2load<8 * G + 6, HALF>(row, src); float v6 = p2v<8 * G + 6, HALF>(row);
        p2load<8 * G + 7, HALF>(row, src); float v7 = p2v<8 * G + 7, HALF>(row);
        float gm = fmaxf(fmaxf(fmaxf(v0, v1), fmaxf(v2, v3)),
                         fmaxf(fmaxf(v4, v5), fmaxf(v6, v7)));
        if (gm > best) { best = gm; bestGS = baseIdx + 8 * G; } // strict '>': earliest group
        p2super<G + 1, HALF>(row, src, best, bestGS, baseIdx);
    }
}

__global__ void __launch_bounds__(NT, 6) kp_kernel(
    const float* __restrict__ masks,
    const float* __restrict__ boxes,
    float* __restrict__ out)
{
    __shared__ float s_mask[(HIN + 2 * MPAD) * HIN];  // 13.4 KB, padded rows
    __shared__ float s_tmp[OUT * TS];                 // 21 KB
    __shared__ float s_rv[NT / 32];
    __shared__ int   s_ri[NT / 32];

    const int tid  = threadIdx.x;
    const int map0 = blockIdx.x * MPC;

    unsigned int smask_u = (unsigned int)__cvta_generic_to_shared(s_mask);

    prefetch_mask(smask_u, masks, map0, tid);
    cp_commit();

    for (int m = 0; m < MPC; m++) {
        const int map = map0 + m;
        const int r_  = map / K_;
        const int k_  = map - r_ * K_;
        const float4 bx = *(const float4*)(boxes + r_ * 4);   // hoisted box load

        cp_wait0();
        __syncthreads();    // mask visible; s_tmp/s_rv free

        // ---- pass 1: 224 threads, two teams split each 12-row period ----
        {
            int team = tid / 112;            // 0: T=0..5, 1: T=6..11
            int rr   = tid - team * 112;
            int g = rr / 14;                 // 0..7 period block
            int q = rr - g * 14;             // 0..13 column quad
            const float* smg = s_mask + (MPAD + 7 * g) * HIN + 4 * q;
            float* dst = s_tmp + (12 * g) * TS + 4 * q;
            float4 rwin[4];
            if (team == 0) p1_team<0, 0, 6 >(rwin, smg, dst);
            else           p1_team<6, 6, 12>(rwin, smg, dst);
        }
        __syncthreads();

        // ---- prefetch next map's mask (overlaps pass 2) ----
        if (m + 1 < MPC) prefetch_mask(smask_u, masks, map + 1, tid);
        cp_commit();

        // ---- pass 2: horizontal 56->96 with supergrouped argmax ----
        float best = -FLT_MAX;
        int bestGS = 0x7fffffff;
        if (tid < 192) {
            int half = tid / 96;             // warp-uniform
            int h    = tid - half * 96;
            float row[32];
            if (half == 0) {
                const float4* src = (const float4*)(s_tmp + h * TS);
                p2super<0, 0>(row, src, best, bestGS, h * OUT);
            } else {
                const float4* src = (const float4*)(s_tmp + h * TS + 24);
                p2super<0, 1>(row, src, best, bestGS, h * OUT + 48);
            }
        }

        #pragma unroll
        for (int off = 16; off > 0; off >>= 1) {
            float ov = __shfl_down_sync(0xffffffffu, best, off);
            int   og = __shfl_down_sync(0xffffffffu, bestGS, off);
            if (ov > best || (ov == best && og < bestGS)) { best = ov; bestGS = og; }
        }
        if ((tid & 31) == 0) { s_rv[tid >> 5] = best; s_ri[tid >> 5] = bestGS; }
        __syncthreads();

        // ---- distributed tail: warp 0 reduces partials + parallel recovery ----
        if (tid < 32) {
            int lane = tid;
            float bv = (lane < NT / 32) ? s_rv[lane] : -FLT_MAX;
            int   bg = (lane < NT / 32) ? s_ri[lane] : 0x7fffffff;
            #pragma unroll
            for (int off = 4; off > 0; off >>= 1) {
                float ov = __shfl_down_sync(0xffffffffu, bv, off);
                int   og = __shfl_down_sync(0xffffffffu, bg, off);
                if (ov > bv || (ov == bv && og < bg)) { bv = ov; bg = og; }
            }
            float bestAll = __shfl_sync(0xffffffffu, bv, 0);
            int   gs      = __shfl_sync(0xffffffffu, bg, 0);

            int hh = gs / OUT;
            int w0 = gs - hh * OUT;
            float v = -FLT_MAX;
            if (lane < 8) {      // lanes recompute the 8 candidates in parallel
                int T = w0 + lane;
                int d = T / 12;
                int t = T - 12 * d;
                int base = 7 * d + cWT.b[t] - 1;
                const float* rowp = s_tmp + hh * TS;
                float x0 = rowp[min(max(base + 0, 0), 55)];
                float x1 = rowp[min(max(base + 1, 0), 55)];
                float x2 = rowp[min(max(base + 2, 0), 55)];
                float x3 = rowp[min(max(base + 3, 0), 55)];
                v = fmaf(x3, cWT.w[t][3],
                    fmaf(x2, cWT.w[t][2],
                    fmaf(x1, cWT.w[t][1], x0 * cWT.w[t][0])));
            }
            unsigned ball = __ballot_sync(0xffffffffu, v == bestAll);
            int found = __ffs(ball) - 1;     // lowest lane = first (smallest) index

            if (lane == 0) {
                int bestIdx = gs + found;
                float len0 = fmaxf(bx.z - bx.x, 1.0f);
                float len1 = fmaxf(bx.w - bx.y, 1.0f);
                int y = bestIdx / OUT;
                int x = bestIdx - y * OUT;
                float p0 = ((float)y + 0.5f) * (len0 / (float)OUT) + bx.x;
                float p1 = ((float)x + 0.5f) * (len1 / (float)OUT) + bx.y;

                float* pred   = out;                    // [R, 3, K]
                float* scores = out + R_ * 3 * K_;      // [R, K]
                pred[r_ * 3 * K_ + 0 * K_ + k_] = p0;
                pred[r_ * 3 * K_ + 1 * K_ + k_] = p1;
                pred[r_ * 3 * K_ + 2 * K_ + k_] = 1.0f;
                scores[r_ * K_ + k_] = bestAll;
            }
        }
    }
}

extern "C" void kernel_launch(void* const* d_in, const int* in_sizes, int n_in,
                              void* d_out, int out_size) {
    const float* masks = (const float*)d_in[0];   // [512,17,56,56] f32
    const float* boxes = (const float*)d_in[1];   // [512,4] f32
    float* out = (float*)d_out;
    kp_kernel<<<NMAP / MPC, NT>>>(masks, boxes, out);
}